// round 7
// baseline (speedup 1.0000x reference)
#include <cuda_runtime.h>

#define N_NODES 61440
#define NB      2048
#define NT      30
#define E_EDGES 491520

// ---------------- scratch (device globals; no runtime allocation) ----------
__device__ float g_deg [N_NODES];
__device__ float g_dinv[N_NODES];
__device__ float g_h   [N_NODES * 12];
__device__ float g_acc [N_NODES * 12];
__device__ float g_X0  [NB * 12  * NT];
__device__ float g_X1  [NB * 128 * NT];
__device__ float g_X2  [NB * 512 * NT];
__device__ float g_X3  [NB * 128 * NT];

// ---------------- GCN ------------------------------------------------------
__global__ void k_init_deg() {
    int i = blockIdx.x * blockDim.x + threadIdx.x;
    if (i < N_NODES) g_deg[i] = 1.0f;   // self-loop
}

// NOTE: edge_index is int32 (JAX x64 disabled downcasts jnp.int64 -> int32)
__global__ void k_count(const int* __restrict__ ei) {
    int e = blockIdx.x * blockDim.x + threadIdx.x;
    if (e < E_EDGES) {
        int dst = ei[E_EDGES + e];
        atomicAdd(&g_deg[dst], 1.0f);
    }
}

__global__ void k_h(const float* __restrict__ x, const float* __restrict__ w) {
    int n = blockIdx.x * blockDim.x + threadIdx.x;
    if (n >= N_NODES) return;
    float xv[12];
#pragma unroll
    for (int j = 0; j < 12; j++) xv[j] = x[n * 12 + j];
    float dinv = rsqrtf(g_deg[n]);
    g_dinv[n] = dinv;
    float s = dinv * dinv;
#pragma unroll
    for (int c = 0; c < 12; c++) {
        float acc = 0.f;
#pragma unroll
        for (int j = 0; j < 12; j++) acc += xv[j] * __ldg(&w[c * 12 + j]);
        g_h[n * 12 + c]   = acc;
        g_acc[n * 12 + c] = s * acc;    // self-loop contribution
    }
}

__global__ void k_scatter(const int* __restrict__ ei) {
    int e = blockIdx.x * blockDim.x + threadIdx.x;
    if (e >= E_EDGES) return;
    int src = ei[e];
    int dst = ei[E_EDGES + e];
    float norm = g_dinv[src] * g_dinv[dst];
    const float4* hs = (const float4*)&g_h[src * 12];
    float4 a = hs[0], b = hs[1], c = hs[2];
    float* ad = &g_acc[dst * 12];
    atomicAdd(ad + 0,  norm * a.x);  atomicAdd(ad + 1,  norm * a.y);
    atomicAdd(ad + 2,  norm * a.z);  atomicAdd(ad + 3,  norm * a.w);
    atomicAdd(ad + 4,  norm * b.x);  atomicAdd(ad + 5,  norm * b.y);
    atomicAdd(ad + 6,  norm * b.z);  atomicAdd(ad + 7,  norm * b.w);
    atomicAdd(ad + 8,  norm * c.x);  atomicAdd(ad + 9,  norm * c.y);
    atomicAdd(ad + 10, norm * c.z);  atomicAdd(ad + 11, norm * c.w);
}

// node-major [n][c] -> [b][c][t] layout for TCN, add bias
__global__ void k_trans(const float* __restrict__ gb) {
    int i = blockIdx.x * blockDim.x + threadIdx.x;
    if (i >= NB * 12 * NT) return;
    int b = i / (12 * NT);
    int r = i - b * 12 * NT;
    int c = r / NT;
    int t = r - c * NT;
    g_X0[i] = g_acc[(b * NT + t) * 12 + c] + gb[c];
}

// ---------------- TCN block ------------------------------------------------
// out = relu( relu(conv_dilated(X)+cb) + (down1x1(X)+db) )
// grid: (NB/G, COUT/128)   block: 128*G threads. thread = (co within 128, g)
template <int CIN, int COUT, int DIL, int G, int CICH>
__global__ void k_tcn(const float* __restrict__ Xin,
                      const float* __restrict__ cw, const float* __restrict__ cb,
                      const float* __restrict__ dw, const float* __restrict__ db,
                      float* __restrict__ Xout) {
    extern __shared__ float sm[];
    float* ws = sm;                       // [CICH][4][128] : k0,k1,k2,down
    float* xs = sm + CICH * 4 * 128;      // [G][CICH][NT]
    const int tid  = threadIdx.x;
    const int cow  = tid & 127;
    const int g    = tid >> 7;
    const int co   = blockIdx.y * 128 + cow;
    const int b0   = blockIdx.x * G;
    const int NTH  = 128 * G;

    float accC[NT], accD[NT];
#pragma unroll
    for (int t = 0; t < NT; t++) { accC[t] = 0.f; accD[t] = 0.f; }

    for (int ci0 = 0; ci0 < CIN; ci0 += CICH) {
        __syncthreads();
        // stage conv weights (coalesced global, conflict-free smem layout)
        for (int e = tid; e < 128 * CICH * 3; e += NTH) {
            int co_ = e / (CICH * 3);
            int r   = e - co_ * (CICH * 3);
            int ci  = r / 3, k = r - ci * 3;
            ws[(ci * 4 + k) * 128 + co_] =
                cw[((blockIdx.y * 128 + co_) * CIN + ci0 + ci) * 3 + k];
        }
        // stage downsample weights
        for (int e = tid; e < 128 * CICH; e += NTH) {
            int co_ = e / CICH;
            int ci  = e - co_ * CICH;
            ws[(ci * 4 + 3) * 128 + co_] =
                dw[(blockIdx.y * 128 + co_) * CIN + ci0 + ci];
        }
        // stage input chunk for G batches
        for (int e = tid; e < G * CICH * NT; e += NTH) {
            int g_ = e / (CICH * NT);
            int r  = e - g_ * (CICH * NT);
            int ci = r / NT, t = r - ci * NT;
            xs[e] = Xin[(long)(b0 + g_) * CIN * NT + (ci0 + ci) * NT + t];
        }
        __syncthreads();

#pragma unroll 2
        for (int ci = 0; ci < CICH; ci++) {
            float w0 = ws[(ci * 4 + 0) * 128 + cow];
            float w1 = ws[(ci * 4 + 1) * 128 + cow];
            float w2 = ws[(ci * 4 + 2) * 128 + cow];
            float wd = ws[(ci * 4 + 3) * 128 + cow];
            const float* xr = &xs[(g * CICH + ci) * NT];
#pragma unroll
            for (int t = 0; t < NT; t++) {
                float xv = xr[t];
                accD[t] += wd * xv;
                accC[t] += w2 * xv;                               // tap k=2 -> +0
                if (t + DIL     < NT) accC[t + DIL]     += w1 * xv; // k=1 -> +d
                if (t + 2 * DIL < NT) accC[t + 2 * DIL] += w0 * xv; // k=0 -> +2d
            }
        }
    }

    float cbv = cb[co], dbv = db[co];
    float* out = &Xout[(long)(b0 + g) * COUT * NT + co * NT];
#pragma unroll
    for (int t = 0; t < NT; t++) {
        float v = fmaxf(accC[t] + cbv, 0.0f) + accD[t] + dbv;
        out[t] = fmaxf(v, 0.0f);
    }
}

// ---------------- FC -------------------------------------------------------
// out[b][o] = sum_j X3[b][j] * fw[o][j] + fb[o], j = c*30+t (matches layout)
// grid: 256 CTAs (8 batches each), block: 256 (8 warps x 9 outputs)
__global__ void k_fc(const float* __restrict__ X, const float* __restrict__ fw,
                     const float* __restrict__ fb, float* __restrict__ out) {
    extern __shared__ float xs[];            // [8][3840]
    const int tid = threadIdx.x;
    const int b0  = blockIdx.x * 8;
    for (int e = tid; e < 8 * 3840; e += 256)
        xs[e] = X[(long)b0 * 3840 + e];
    __syncthreads();

    const int w    = tid >> 5;
    const int lane = tid & 31;
    const int o0   = w * 9;
    float acc[9][8];
#pragma unroll
    for (int r = 0; r < 9; r++)
#pragma unroll
        for (int g2 = 0; g2 < 8; g2++) acc[r][g2] = 0.f;

    for (int it = 0; it < 120; it++) {
        int j = it * 32 + lane;
        float xj[8];
#pragma unroll
        for (int g2 = 0; g2 < 8; g2++) xj[g2] = xs[g2 * 3840 + j];
#pragma unroll
        for (int r = 0; r < 9; r++) {
            float wv = fw[(o0 + r) * 3840 + j];
#pragma unroll
            for (int g2 = 0; g2 < 8; g2++) acc[r][g2] += wv * xj[g2];
        }
    }
#pragma unroll
    for (int r = 0; r < 9; r++) {
#pragma unroll
        for (int g2 = 0; g2 < 8; g2++) {
            float v = acc[r][g2];
            for (int off = 16; off; off >>= 1)
                v += __shfl_xor_sync(0xffffffff, v, off);
            if (lane == 0)
                out[(b0 + g2) * 72 + o0 + r] = v + fb[o0 + r];
        }
    }
}

// ---------------- launch ---------------------------------------------------
extern "C" void kernel_launch(void* const* d_in, const int* in_sizes, int n_in,
                              void* d_out, int out_size) {
    const float* x   = (const float*)d_in[0];
    const int*   ei  = (const int*)d_in[1];     // int32! (JAX x64 disabled)
    const float* gw  = (const float*)d_in[2];
    const float* gb  = (const float*)d_in[3];
    const float* cw0 = (const float*)d_in[4];
    const float* cb0 = (const float*)d_in[5];
    const float* dw0 = (const float*)d_in[6];
    const float* db0 = (const float*)d_in[7];
    const float* cw1 = (const float*)d_in[8];
    const float* cb1 = (const float*)d_in[9];
    const float* dw1 = (const float*)d_in[10];
    const float* db1 = (const float*)d_in[11];
    const float* cw2 = (const float*)d_in[12];
    const float* cb2 = (const float*)d_in[13];
    const float* dw2 = (const float*)d_in[14];
    const float* db2 = (const float*)d_in[15];
    const float* fw  = (const float*)d_in[16];
    const float* fb  = (const float*)d_in[17];
    float* out = (float*)d_out;

    float *pX0, *pX1, *pX2, *pX3;
    cudaGetSymbolAddress((void**)&pX0, g_X0);
    cudaGetSymbolAddress((void**)&pX1, g_X1);
    cudaGetSymbolAddress((void**)&pX2, g_X2);
    cudaGetSymbolAddress((void**)&pX3, g_X3);

    // dynamic smem opt-in (idempotent; done every call)
    const int smem0 = (12 * 4 * 128 + 4 * 12 * NT) * 4;   // 30336
    const int smem1 = (32 * 4 * 128 + 4 * 32 * NT) * 4;   // 80896
    const int smemF = 8 * 3840 * 4;                       // 122880
    cudaFuncSetAttribute(k_tcn<128, 512, 3, 4, 32>,
                         cudaFuncAttributeMaxDynamicSharedMemorySize, smem1);
    cudaFuncSetAttribute(k_tcn<512, 128, 9, 4, 32>,
                         cudaFuncAttributeMaxDynamicSharedMemorySize, smem1);
    cudaFuncSetAttribute(k_fc,
                         cudaFuncAttributeMaxDynamicSharedMemorySize, smemF);

    // ---- GCN ----
    k_init_deg<<<(N_NODES + 255) / 256, 256>>>();
    k_count<<<(E_EDGES + 255) / 256, 256>>>(ei);
    k_h<<<(N_NODES + 255) / 256, 256>>>(x, gw);
    k_scatter<<<(E_EDGES + 255) / 256, 256>>>(ei);
    k_trans<<<(NB * 12 * NT + 255) / 256, 256>>>(gb);

    // ---- TCN ----
    k_tcn<12, 128, 1, 4, 12><<<dim3(NB / 4, 1), 512, smem0>>>(pX0, cw0, cb0, dw0, db0, pX1);
    k_tcn<128, 512, 3, 4, 32><<<dim3(NB / 4, 4), 512, smem1>>>(pX1, cw1, cb1, dw1, db1, pX2);
    k_tcn<512, 128, 9, 4, 32><<<dim3(NB / 4, 1), 512, smem1>>>(pX2, cw2, cb2, dw2, db2, pX3);

    // ---- FC (final relu is identity: X3 >= 0 already) ----
    k_fc<<<NB / 8, 256, smemF>>>(pX3, fw, fb, out);
}